// round 14
// baseline (speedup 1.0000x reference)
#include <cuda_runtime.h>
#include <cuda_fp16.h>
#include <cstdint>

#define THREADS 128
#define BLOCKS  1024              // 2 tiles per block exactly (NTILES=2048)
#define NPTS    (512 * 512)
#define NTILES  2048              // 128 points per block-tile

// ---- smem byte layout ----
#define OFF_ABUF  0               // 4 warps x 32 rows x 128B = 16384
#define OFF_L0    16384           // power-basis L0: 2 i x 10 j x 528B = 10560
#define OFF_L0SB  26944           // sb0 pairs: 2 i x 16 q x 8B = 256
#define OFF_L2    27200           // power-basis L2: 16 rows x 528B = 8448
#define OFF_L2SB  35648           // 32 f32 = 128
#define SMEM_BYTES 35776          // x6 CTAs = 214656 <= 228KB

// B fragments live in global, cached in L1 (shared by all CTAs on an SM)
__device__ uint32_t g_bfrag[8192];

// ---------------- helpers ----------------
typedef unsigned long long u64;
__device__ __forceinline__ uint32_t smem_u32(const void* p) {
    uint32_t a;
    asm("{ .reg .u64 t; cvta.to.shared.u64 t, %1; cvt.u32.u64 %0, t; }" : "=r"(a) : "l"(p));
    return a;
}
__device__ __forceinline__ void sts32(uint32_t a, uint32_t v) {
    asm volatile("st.shared.b32 [%0], %1;" :: "r"(a), "r"(v) : "memory");
}
__device__ __forceinline__ void sts16(uint32_t a, uint16_t v) {
    asm volatile("st.shared.b16 [%0], %1;" :: "r"(a), "h"(v) : "memory");
}
__device__ __forceinline__ void sts128z(uint32_t a) {
    asm volatile("st.shared.v4.b32 [%0], {%1,%1,%1,%1};" :: "r"(a), "r"(0u) : "memory");
}
__device__ __forceinline__ void lds128f(float& a, float& b, float& c, float& d, uint32_t addr) {
    asm volatile("ld.shared.v4.f32 {%0,%1,%2,%3}, [%4];"
                 : "=f"(a), "=f"(b), "=f"(c), "=f"(d) : "r"(addr));
}
__device__ __forceinline__ void lds128u64(u64& a, u64& b, uint32_t addr) {
    asm volatile("ld.shared.v2.b64 {%0,%1}, [%2];" : "=l"(a), "=l"(b) : "r"(addr));
}
__device__ __forceinline__ u64 lds_b64(uint32_t a) {
    u64 v;
    asm volatile("ld.shared.b64 %0, [%1];" : "=l"(v) : "r"(a));
    return v;
}
__device__ __forceinline__ void ldmatrix_x4(uint32_t& r0, uint32_t& r1, uint32_t& r2, uint32_t& r3,
                                            uint32_t addr) {
    asm volatile("ldmatrix.sync.aligned.m8n8.x4.shared.b16 {%0,%1,%2,%3}, [%4];"
                 : "=r"(r0), "=r"(r1), "=r"(r2), "=r"(r3) : "r"(addr));
}
__device__ __forceinline__ void mma16816(float* d, const uint32_t* a, uint32_t b0, uint32_t b1) {
    asm volatile("mma.sync.aligned.m16n8k16.row.col.f32.f16.f16.f32 "
                 "{%0,%1,%2,%3}, {%4,%5,%6,%7}, {%8,%9}, {%0,%1,%2,%3};"
                 : "+f"(d[0]), "+f"(d[1]), "+f"(d[2]), "+f"(d[3])
                 : "r"(a[0]), "r"(a[1]), "r"(a[2]), "r"(a[3]), "r"(b0), "r"(b1));
}
__device__ __forceinline__ u64 pack2(float lo, float hi) {
    u64 r;
    asm("mov.b64 %0, {%1,%2};" : "=l"(r) : "f"(lo), "f"(hi));
    return r;
}
__device__ __forceinline__ void fma2(u64& acc, u64 a, u64 b) {
    asm("fma.rn.f32x2 %0, %1, %2, %0;" : "+l"(acc) : "l"(a), "l"(b));
}
__device__ __forceinline__ u64 fma2g(u64 a, u64 b, u64 c) {
    u64 d;
    asm("fma.rn.f32x2 %0, %1, %2, %3;" : "=l"(d) : "l"(a), "l"(b), "l"(c));
    return d;
}
__device__ __forceinline__ u64 add2(u64 a, u64 b) {
    u64 d;
    asm("add.rn.f32x2 %0, %1, %2;" : "=l"(d) : "l"(a), "l"(b));
    return d;
}
__device__ __forceinline__ void unpack2(u64 v, float& lo, float& hi) {
    asm("mov.b64 {%0,%1}, %2;" : "=f"(lo), "=f"(hi) : "l"(v));
}
__device__ __forceinline__ float sigmoidf_(float x) { return 1.0f / (1.0f + __expf(-x)); }
__device__ __forceinline__ uint32_t h2bits(float lo, float hi) {
    __half2 h = __floats2half2_rn(lo, hi);
    return *reinterpret_cast<uint32_t*>(&h);
}

// raw uniform cubic B-spline polys (no tap zeroing); oor -> j=-3, t=0
__device__ __forceinline__ void spline_raw(float x, float& b0, float& b1, float& b2, float& b3,
                                           int& j)
{
    float u = x * 10.0f;
    bool inr = (u >= -3.0f) && (u < 13.0f);
    float uc = inr ? u : 0.0f;
    float f = floorf(uc);
    float t = uc - f;
    j = inr ? (int)f : -3;
    if (!inr) t = 0.0f;
    const float C6 = 0.16666667f;
    float t2 = t * t, t3 = t2 * t;
    float omt = 1.0f - t;
    b0 = omt * omt * omt * C6;
    b1 = (3.0f * t3 - 6.0f * t2 + 4.0f) * C6;
    b2 = ((3.0f - 3.0f * t) * t2 + 3.0f * t + 1.0f) * C6;
    b3 = t3 * C6;
}

// power-basis coefficients from 4 taps C0..C3 (spline = c0 + c1 t + c2 t^2 + c3 t^3)
__device__ __forceinline__ void pb_coeffs(const float* C, float& c0, float& c1, float& c2, float& c3)
{
    const float C6 = 0.16666667f;
    c0 = (C[0] + 4.0f * C[1] + C[2]) * C6;
    c1 = (C[2] - C[0]) * 0.5f;
    c2 = (C[0] - 2.0f * C[1] + C[2]) * 0.5f;
    c3 = (-C[0] + 3.0f * C[1] - 3.0f * C[2] + C[3]) * C6;
}

// ---------------- init kernel: stage B fragments to global ----------------
__global__ void bfrag_init(const float* __restrict__ sb1, const float* __restrict__ sp1,
                           const float* __restrict__ coef1)
{
    int e = blockIdx.x * blockDim.x + threadIdx.x;
    if (e >= 8192) return;
    int L = e & 31, reg = (e >> 5) & 1, nt = (e >> 6) & 3, kt = e >> 8;
    int k = kt * 16 + 2 * (L & 3) + 8 * reg;
    int n = nt * 8 + (L >> 2);
    float w[2];
#pragma unroll
    for (int z = 0; z < 2; z++) {
        int f = k + z;
        int i = f >> 4, r = f & 15;
        float v = 0.0f;
        if (r == 0)       v = sb1[i * 32 + n];
        else if (r <= 13) v = sp1[i * 32 + n] * coef1[(i * 32 + n) * 13 + (r - 1)];
        w[z] = v;
    }
    g_bfrag[(kt * 2 + (nt >> 1)) * 128 + L * 4 + (nt & 1) * 2 + reg] = h2bits(w[0], w[1]);
}

// ---------------- main kernel ----------------
__global__ void __launch_bounds__(THREADS, 6)
kan_forward(const float* __restrict__ coords,
            const float* __restrict__ coef0, const float* __restrict__ sb0, const float* __restrict__ sp0,
            const float* __restrict__ coef2, const float* __restrict__ sb2, const float* __restrict__ sp2,
            const float* __restrict__ dbias,
            float* __restrict__ out)
{
    extern __shared__ char smem[];
    float* smf = reinterpret_cast<float*>(smem);
    const uint32_t sbase = smem_u32(smem);
    const int tid  = threadIdx.x;
    const int wid  = tid >> 5;
    const int lane = tid & 31;

    // ======== one-time staging ========
    // L0 power-basis: [i][j][q]{c3,c3',c2,c2',c1,c1',c0,c0'}; j stride 528B
    for (int idx = tid; idx < 320; idx += THREADS) {
        int i = idx / 160, r = idx % 160, j = r / 16, q = r % 16;
        int fo = (OFF_L0 + i * 5280 + j * 528 + q * 32) / 4;
#pragma unroll
        for (int z = 0; z < 2; z++) {
            int o = 2 * q + z;
            float C[4];
#pragma unroll
            for (int d = 0; d < 4; d++)
                C[d] = sp0[i * 32 + o] * coef0[(i * 32 + o) * 13 + j + d];
            float c0, c1, c2, c3;
            pb_coeffs(C, c0, c1, c2, c3);
            smf[fo + 0 + z] = c3;
            smf[fo + 2 + z] = c2;
            smf[fo + 4 + z] = c1;
            smf[fo + 6 + z] = c0;
        }
    }
    // L0 sb pairs
    for (int idx = tid; idx < 32; idx += THREADS) {
        int i = idx / 16, q = idx % 16;
        smf[(OFF_L0SB + i * 128 + q * 8) / 4 + 0] = sb0[i * 32 + 2 * q];
        smf[(OFF_L0SB + i * 128 + q * 8) / 4 + 1] = sb0[i * 32 + 2 * q + 1];
    }
    // L2 power-basis: [row 0..15][col]{c3,c2,c1,c0}; row stride 528B; C zero-extended
    for (int idx = tid; idx < 512; idx += THREADS) {
        int r = idx >> 5, col = idx & 31, j = r - 3;
        float C[4];
#pragma unroll
        for (int d = 0; d < 4; d++) {
            int k = j + d;
            C[d] = (k >= 0 && k <= 12) ? sp2[col] * coef2[col * 13 + k] : 0.0f;
        }
        float c0, c1, c2, c3;
        pb_coeffs(C, c0, c1, c2, c3);
        int fo = (OFF_L2 + r * 528 + col * 16) / 4;
        smf[fo + 0] = c3;
        smf[fo + 1] = c2;
        smf[fo + 2] = c1;
        smf[fo + 3] = c0;
    }
    for (int idx = tid; idx < 32; idx += THREADS)
        smf[OFF_L2SB / 4 + idx] = sb2[idx];
    __syncthreads();

    const float bias = dbias[0];
    const uint32_t ABw     = sbase + OFF_ABUF + (uint32_t)wid * 4096u;
    const uint32_t rowbase = ABw + (uint32_t)lane * 128u;
    const uint32_t swzm    = (uint32_t)(lane & 7) << 4;
    const int lrow  = lane & 15;
    const int lcolb = (lane >> 4) * 16;
    const uint32_t rmask = (uint32_t)(lrow & 7) << 4;
    const uint32_t lmA0 = ABw + (uint32_t)lrow * 128u;
    const uint32_t lmA1 = ABw + (uint32_t)(16 + lrow) * 128u;
    const uint4* Bg = reinterpret_cast<const uint4*>(g_bfrag) + lane;

    for (int tile = blockIdx.x; tile < NTILES; tile += BLOCKS) {
        const int pbase = tile * 128 + wid * 32;
        const int p = pbase + lane;

        // ---- layer-0 prep (coords in [0,1) -> j in 0..9) ----
        float2 cc = reinterpret_cast<const float2*>(coords)[p];
        u64 tp[2], bp[2];
        uint32_t Tr[2];
#pragma unroll
        for (int i = 0; i < 2; i++) {
            float x = (i == 0) ? cc.x : cc.y;
            float u = x * 10.0f;
            float fl = floorf(u);
            float t = u - fl;
            int j = (int)fl;
            tp[i] = pack2(t, t);
            float base = x * sigmoidf_(x);
            bp[i] = pack2(base, base);
            Tr[i] = sbase + OFF_L0 + (uint32_t)i * 5280u + (uint32_t)j * 528u;
        }

        // half-chunk hf (0..15): zero 64B segment, compute 2 h1 outputs, scatter
        auto do_half = [&](int hf) {
            const uint32_t seg = (uint32_t)(hf & 1) * 64u;
#pragma unroll
            for (int q = 0; q < 4; q++)
                sts128z(rowbase + ((seg + (uint32_t)q * 16u) ^ swzm));
            float xv[2];
            {
                uint32_t qi = (uint32_t)hf;          // output-pair index
                uint32_t off = qi * 32u;
                u64 h = 0ull;
#pragma unroll
                for (int i = 0; i < 2; i++) {
                    u64 sbp = lds_b64(sbase + OFF_L0SB + (uint32_t)i * 128u + qi * 8u);
                    fma2(h, bp[i], sbp);
                    u64 c3p, c2p, c1p, c0p;
                    lds128u64(c3p, c2p, Tr[i] + off);
                    lds128u64(c1p, c0p, Tr[i] + off + 16u);
                    u64 s = fma2g(c3p, tp[i], c2p);
                    s = fma2g(s, tp[i], c1p);
                    s = fma2g(s, tp[i], c0p);
                    h = add2(h, s);
                }
                unpack2(h, xv[0], xv[1]);
            }
            // guard-free scatter (invalid taps absorbed by wi guards / dummy slots /
            // slot 0 overwritten by silu)
#pragma unroll
            for (int il = 0; il < 2; il++) {
                float x = xv[il];
                float b0, b1, b2, b3; int j;
                spline_raw(x, b0, b1, b2, b3, j);
                float base = x * sigmoidf_(x);
                uint32_t u01 = h2bits(b0, b1);
                uint32_t u23 = h2bits(b2, b3);
                int s1 = 1 + j;
                int wi = s1 >> 1;
                bool odd = (s1 & 1) != 0;
                uint32_t v1 = odd ? (u01 << 16) : u01;
                uint32_t v2 = odd ? ((u01 >> 16) | (u23 << 16)) : u23;
                uint32_t v3 = odd ? (u23 >> 16) : 0u;
                uint32_t bb = seg + (uint32_t)(32 * il);
                if (wi >= 0) sts32(rowbase + ((bb + 4u * (uint32_t)wi) ^ swzm), v1);
                sts32(rowbase + ((bb + 4u * (uint32_t)(wi + 1)) ^ swzm), v2);
                if (wi <= 5) sts32(rowbase + ((bb + 4u * (uint32_t)(wi + 2)) ^ swzm), v3);
                __half hs = __float2half_rn(base);
                sts16(rowbase + (bb ^ swzm), __half_as_ushort(hs));
            }
        };

        // ---- layer 1: half-chunk pipelined GEMM D[32x32] = A[32x512] * B ----
        float acc[2][4][4];
#pragma unroll
        for (int mt = 0; mt < 2; mt++)
#pragma unroll
            for (int nt = 0; nt < 4; nt++)
#pragma unroll
                for (int e = 0; e < 4; e++) acc[mt][nt][e] = 0.0f;

        do_half(0);

#pragma unroll 1
        for (int hf = 0; hf < 16; hf++) {
            __syncwarp();                 // scatter(hf) visible
            uint32_t afr[2][2][4];
            const uint32_t seg = (uint32_t)(hf & 1) * 64u;
#pragma unroll
            for (int kt = 0; kt < 2; kt++) {
                uint32_t inrow = ((seg + (uint32_t)(kt * 32 + lcolb))) ^ rmask;
                ldmatrix_x4(afr[kt][0][0], afr[kt][0][1], afr[kt][0][2], afr[kt][0][3],
                            lmA0 + inrow);
                ldmatrix_x4(afr[kt][1][0], afr[kt][1][1], afr[kt][1][2], afr[kt][1][3],
                            lmA1 + inrow);
            }
            __syncwarp();                 // segment reads done -> reusable
            if (hf < 15) do_half(hf + 1); // overlaps with mma below
#pragma unroll
            for (int kt = 0; kt < 2; kt++) {
                int ktg = hf * 2 + kt;
#pragma unroll
                for (int np = 0; np < 2; np++) {
                    uint4 bv = __ldg(Bg + (ktg * 2 + np) * 32);
                    mma16816(acc[0][2 * np],     afr[kt][0], bv.x, bv.y);
                    mma16816(acc[1][2 * np],     afr[kt][1], bv.x, bv.y);
                    mma16816(acc[0][2 * np + 1], afr[kt][0], bv.z, bv.w);
                    mma16816(acc[1][2 * np + 1], afr[kt][1], bv.z, bv.w);
                }
            }
        }

        // ---- layer 2 in fragment space (power-basis Horner) ----
        const float* S2 = smf + OFF_L2SB / 4;
        float ps[4] = {0.0f, 0.0f, 0.0f, 0.0f};
#pragma unroll
        for (int mt = 0; mt < 2; mt++)
#pragma unroll
            for (int nt = 0; nt < 4; nt++)
#pragma unroll
                for (int e = 0; e < 4; e++) {
                    float x = acc[mt][nt][e];
                    int col = nt * 8 + 2 * (lane & 3) + (e & 1);
                    float u = x * 10.0f;
                    bool inr = (u >= -3.0f) && (u < 13.0f);
                    float uc = inr ? u : 0.0f;
                    float fl = floorf(uc);
                    float t = uc - fl;
                    int r = (int)fl + 3;       // 0..15 when in range
                    float c3, c2, c1, c0;
                    lds128f(c3, c2, c1, c0,
                            sbase + OFF_L2 + (uint32_t)r * 528u + (uint32_t)col * 16u);
                    float s = fmaf(c3, t, c2);
                    s = fmaf(s, t, c1);
                    s = fmaf(s, t, c0);
                    s = inr ? s : 0.0f;
                    float base = x * sigmoidf_(x);
                    float g = fmaf(S2[col], base, s);
                    ps[mt * 2 + (e >> 1)] += g;
                }
#pragma unroll
        for (int s = 0; s < 4; s++) {
            ps[s] += __shfl_xor_sync(0xffffffffu, ps[s], 1);
            ps[s] += __shfl_xor_sync(0xffffffffu, ps[s], 2);
        }
        if ((lane & 3) == 0) {
#pragma unroll
            for (int s = 0; s < 4; s++) {
                int row = 16 * (s >> 1) + 8 * (s & 1) + (lane >> 2);
                out[pbase + row] = sigmoidf_(ps[s] + bias);
            }
        }
    }
}

extern "C" void kernel_launch(void* const* d_in, const int* in_sizes, int n_in,
                              void* d_out, int out_size)
{
    // order: coords, grid0, coef0, sb0, sp0, grid1, coef1, sb1, sp1, grid2, coef2, sb2, sp2, density_bias
    const float* coords = (const float*)d_in[0];
    const float* coef0  = (const float*)d_in[2];
    const float* sb0    = (const float*)d_in[3];
    const float* sp0    = (const float*)d_in[4];
    const float* coef1  = (const float*)d_in[6];
    const float* sb1    = (const float*)d_in[7];
    const float* sp1    = (const float*)d_in[8];
    const float* coef2  = (const float*)d_in[10];
    const float* sb2    = (const float*)d_in[11];
    const float* sp2    = (const float*)d_in[12];
    const float* dbias  = (const float*)d_in[13];
    float* out = (float*)d_out;

    bfrag_init<<<64, 128>>>(sb1, sp1, coef1);
    cudaFuncSetAttribute(kan_forward, cudaFuncAttributeMaxDynamicSharedMemorySize, SMEM_BYTES);
    kan_forward<<<BLOCKS, THREADS, SMEM_BYTES>>>(coords,
                                                 coef0, sb0, sp0,
                                                 coef2, sb2, sp2,
                                                 dbias, out);
}

// round 15
// speedup vs baseline: 1.0266x; 1.0266x over previous
#include <cuda_runtime.h>
#include <cuda_fp16.h>
#include <cstdint>

#define THREADS 128
#define BLOCKS  740               // 148 SMs * 5 CTAs, single wave
#define NPTS    (512 * 512)
#define NTILES  2048              // 128 points per block-tile

// ---- smem byte layout ----
#define OFF_ABUF  0               // 4 warps x 32 rows x 128B = 16384
#define OFF_L0    16384           // power-basis L0: 2 i x 10 j x 528B = 10560
#define OFF_L0SB  26944           // sb0 pairs: 2 i x 16 q x 8B = 256
#define OFF_L2    27200           // power-basis L2: 16 rows x 528B = 8448
#define OFF_L2SB  35648           // 32 f32 = 128
#define SMEM_BYTES 35776          // x5 CTAs = 178880

// B fragments live in global, cached in L1 (shared by all CTAs on an SM)
__device__ uint32_t g_bfrag[8192];

// ---------------- helpers ----------------
typedef unsigned long long u64;
__device__ __forceinline__ uint32_t smem_u32(const void* p) {
    uint32_t a;
    asm("{ .reg .u64 t; cvta.to.shared.u64 t, %1; cvt.u32.u64 %0, t; }" : "=r"(a) : "l"(p));
    return a;
}
__device__ __forceinline__ void sts32(uint32_t a, uint32_t v) {
    asm volatile("st.shared.b32 [%0], %1;" :: "r"(a), "r"(v) : "memory");
}
__device__ __forceinline__ void sts128z(uint32_t a) {
    asm volatile("st.shared.v4.b32 [%0], {%1,%1,%1,%1};" :: "r"(a), "r"(0u) : "memory");
}
__device__ __forceinline__ void lds128f(float& a, float& b, float& c, float& d, uint32_t addr) {
    asm volatile("ld.shared.v4.f32 {%0,%1,%2,%3}, [%4];"
                 : "=f"(a), "=f"(b), "=f"(c), "=f"(d) : "r"(addr));
}
__device__ __forceinline__ void lds128u64(u64& a, u64& b, uint32_t addr) {
    asm volatile("ld.shared.v2.b64 {%0,%1}, [%2];" : "=l"(a), "=l"(b) : "r"(addr));
}
__device__ __forceinline__ u64 lds_b64(uint32_t a) {
    u64 v;
    asm volatile("ld.shared.b64 %0, [%1];" : "=l"(v) : "r"(a));
    return v;
}
__device__ __forceinline__ void ldmatrix_x4(uint32_t& r0, uint32_t& r1, uint32_t& r2, uint32_t& r3,
                                            uint32_t addr) {
    asm volatile("ldmatrix.sync.aligned.m8n8.x4.shared.b16 {%0,%1,%2,%3}, [%4];"
                 : "=r"(r0), "=r"(r1), "=r"(r2), "=r"(r3) : "r"(addr));
}
__device__ __forceinline__ void mma16816(float* d, const uint32_t* a, uint32_t b0, uint32_t b1) {
    asm volatile("mma.sync.aligned.m16n8k16.row.col.f32.f16.f16.f32 "
                 "{%0,%1,%2,%3}, {%4,%5,%6,%7}, {%8,%9}, {%0,%1,%2,%3};"
                 : "+f"(d[0]), "+f"(d[1]), "+f"(d[2]), "+f"(d[3])
                 : "r"(a[0]), "r"(a[1]), "r"(a[2]), "r"(a[3]), "r"(b0), "r"(b1));
}
__device__ __forceinline__ u64 pack2(float lo, float hi) {
    u64 r;
    asm("mov.b64 %0, {%1,%2};" : "=l"(r) : "f"(lo), "f"(hi));
    return r;
}
__device__ __forceinline__ void fma2(u64& acc, u64 a, u64 b) {
    asm("fma.rn.f32x2 %0, %1, %2, %0;" : "+l"(acc) : "l"(a), "l"(b));
}
__device__ __forceinline__ u64 fma2g(u64 a, u64 b, u64 c) {
    u64 d;
    asm("fma.rn.f32x2 %0, %1, %2, %3;" : "=l"(d) : "l"(a), "l"(b), "l"(c));
    return d;
}
__device__ __forceinline__ u64 add2(u64 a, u64 b) {
    u64 d;
    asm("add.rn.f32x2 %0, %1, %2;" : "=l"(d) : "l"(a), "l"(b));
    return d;
}
__device__ __forceinline__ void unpack2(u64 v, float& lo, float& hi) {
    asm("mov.b64 {%0,%1}, %2;" : "=f"(lo), "=f"(hi) : "l"(v));
}
__device__ __forceinline__ float sigmoidf_(float x) { return 1.0f / (1.0f + __expf(-x)); }
__device__ __forceinline__ uint32_t h2bits(float lo, float hi) {
    __half2 h = __floats2half2_rn(lo, hi);
    return *reinterpret_cast<uint32_t*>(&h);
}

// raw uniform cubic B-spline polys (no tap zeroing); oor -> j=-3, t=0
__device__ __forceinline__ void spline_raw(float x, float& b0, float& b1, float& b2, float& b3,
                                           int& j)
{
    float u = x * 10.0f;
    bool inr = (u >= -3.0f) && (u < 13.0f);
    float uc = inr ? u : 0.0f;
    float f = floorf(uc);
    float t = uc - f;
    j = inr ? (int)f : -3;
    if (!inr) t = 0.0f;
    const float C6 = 0.16666667f;
    float t2 = t * t, t3 = t2 * t;
    float omt = 1.0f - t;
    b0 = omt * omt * omt * C6;
    b1 = (3.0f * t3 - 6.0f * t2 + 4.0f) * C6;
    b2 = ((3.0f - 3.0f * t) * t2 + 3.0f * t + 1.0f) * C6;
    b3 = t3 * C6;
}

// power-basis coefficients from 4 taps C0..C3 (spline = c0 + c1 t + c2 t^2 + c3 t^3)
__device__ __forceinline__ void pb_coeffs(const float* C, float& c0, float& c1, float& c2, float& c3)
{
    const float C6 = 0.16666667f;
    c0 = (C[0] + 4.0f * C[1] + C[2]) * C6;
    c1 = (C[2] - C[0]) * 0.5f;
    c2 = (C[0] - 2.0f * C[1] + C[2]) * 0.5f;
    c3 = (-C[0] + 3.0f * C[1] - 3.0f * C[2] + C[3]) * C6;
}

// ---------------- init kernel: stage B fragments to global ----------------
__global__ void bfrag_init(const float* __restrict__ sb1, const float* __restrict__ sp1,
                           const float* __restrict__ coef1)
{
    int e = blockIdx.x * blockDim.x + threadIdx.x;
    if (e >= 8192) return;
    int L = e & 31, reg = (e >> 5) & 1, nt = (e >> 6) & 3, kt = e >> 8;
    int k = kt * 16 + 2 * (L & 3) + 8 * reg;
    int n = nt * 8 + (L >> 2);
    float w[2];
#pragma unroll
    for (int z = 0; z < 2; z++) {
        int f = k + z;
        int i = f >> 4, r = f & 15;
        float v = 0.0f;
        if (r == 0)       v = sb1[i * 32 + n];
        else if (r <= 13) v = sp1[i * 32 + n] * coef1[(i * 32 + n) * 13 + (r - 1)];
        w[z] = v;
    }
    g_bfrag[(kt * 2 + (nt >> 1)) * 128 + L * 4 + (nt & 1) * 2 + reg] = h2bits(w[0], w[1]);
}

// ---------------- main kernel ----------------
__global__ void __launch_bounds__(THREADS, 5)
kan_forward(const float* __restrict__ coords,
            const float* __restrict__ coef0, const float* __restrict__ sb0, const float* __restrict__ sp0,
            const float* __restrict__ coef2, const float* __restrict__ sb2, const float* __restrict__ sp2,
            const float* __restrict__ dbias,
            float* __restrict__ out)
{
    extern __shared__ char smem[];
    float* smf = reinterpret_cast<float*>(smem);
    const uint32_t sbase = smem_u32(smem);
    const int tid  = threadIdx.x;
    const int wid  = tid >> 5;
    const int lane = tid & 31;

    // ======== one-time staging ========
    // L0 power-basis: [i][j][q]{c3,c3',c2,c2',c1,c1',c0,c0'}; j stride 528B
    for (int idx = tid; idx < 320; idx += THREADS) {
        int i = idx / 160, r = idx % 160, j = r / 16, q = r % 16;
        int fo = (OFF_L0 + i * 5280 + j * 528 + q * 32) / 4;
#pragma unroll
        for (int z = 0; z < 2; z++) {
            int o = 2 * q + z;
            float C[4];
#pragma unroll
            for (int d = 0; d < 4; d++)
                C[d] = sp0[i * 32 + o] * coef0[(i * 32 + o) * 13 + j + d];
            float c0, c1, c2, c3;
            pb_coeffs(C, c0, c1, c2, c3);
            smf[fo + 0 + z] = c3;
            smf[fo + 2 + z] = c2;
            smf[fo + 4 + z] = c1;
            smf[fo + 6 + z] = c0;
        }
    }
    // L0 sb pairs
    for (int idx = tid; idx < 32; idx += THREADS) {
        int i = idx / 16, q = idx % 16;
        smf[(OFF_L0SB + i * 128 + q * 8) / 4 + 0] = sb0[i * 32 + 2 * q];
        smf[(OFF_L0SB + i * 128 + q * 8) / 4 + 1] = sb0[i * 32 + 2 * q + 1];
    }
    // L2 power-basis: [row 0..15][col]{c3,c2,c1,c0}; row stride 528B; C zero-extended
    for (int idx = tid; idx < 512; idx += THREADS) {
        int r = idx >> 5, col = idx & 31, j = r - 3;
        float C[4];
#pragma unroll
        for (int d = 0; d < 4; d++) {
            int k = j + d;
            C[d] = (k >= 0 && k <= 12) ? sp2[col] * coef2[col * 13 + k] : 0.0f;
        }
        float c0, c1, c2, c3;
        pb_coeffs(C, c0, c1, c2, c3);
        int fo = (OFF_L2 + r * 528 + col * 16) / 4;
        smf[fo + 0] = c3;
        smf[fo + 1] = c2;
        smf[fo + 2] = c1;
        smf[fo + 3] = c0;
    }
    for (int idx = tid; idx < 32; idx += THREADS)
        smf[OFF_L2SB / 4 + idx] = sb2[idx];
    __syncthreads();

    const float bias = dbias[0];
    const uint32_t ABw     = sbase + OFF_ABUF + (uint32_t)wid * 4096u;
    const uint32_t rowbase = ABw + (uint32_t)lane * 128u;
    const uint32_t swzm    = (uint32_t)(lane & 7) << 4;
    const int lrow  = lane & 15;
    const int lcolb = (lane >> 4) * 16;
    const uint32_t rmask = (uint32_t)(lrow & 7) << 4;
    const uint32_t lmA0 = ABw + (uint32_t)lrow * 128u;
    const uint32_t lmA1 = ABw + (uint32_t)(16 + lrow) * 128u;
    const uint4* Bg = reinterpret_cast<const uint4*>(g_bfrag) + lane;

    for (int tile = blockIdx.x; tile < NTILES; tile += BLOCKS) {
        const int pbase = tile * 128 + wid * 32;
        const int p = pbase + lane;

        // ---- layer-0 prep (coords in [0,1) -> j in 0..9) ----
        float2 cc = reinterpret_cast<const float2*>(coords)[p];
        u64 tp[2], bp[2];
        uint32_t Tr[2];
#pragma unroll
        for (int i = 0; i < 2; i++) {
            float x = (i == 0) ? cc.x : cc.y;
            float u = x * 10.0f;
            float fl = floorf(u);
            float t = u - fl;
            int j = (int)fl;
            tp[i] = pack2(t, t);
            float base = x * sigmoidf_(x);
            bp[i] = pack2(base, base);
            Tr[i] = sbase + OFF_L0 + (uint32_t)i * 5280u + (uint32_t)j * 528u;
        }

        // zero + compute h1 (4 outputs, Horner power basis) + scatter, for chunk cidx
        auto do_chunk = [&](int cidx) {
#pragma unroll
            for (int q = 0; q < 8; q++)
                sts128z(rowbase + (((uint32_t)q * 16u) ^ swzm));
            float xv[4];
#pragma unroll
            for (int z = 0; z < 2; z++) {
                uint32_t qi = (uint32_t)(2 * cidx + z);
                uint32_t off = qi * 32u;
                u64 h = 0ull;
#pragma unroll
                for (int i = 0; i < 2; i++) {
                    u64 sbp = lds_b64(sbase + OFF_L0SB + (uint32_t)i * 128u + qi * 8u);
                    fma2(h, bp[i], sbp);
                    u64 c3p, c2p, c1p, c0p;
                    lds128u64(c3p, c2p, Tr[i] + off);
                    lds128u64(c1p, c0p, Tr[i] + off + 16u);
                    u64 s = fma2g(c3p, tp[i], c2p);
                    s = fma2g(s, tp[i], c1p);
                    s = fma2g(s, tp[i], c0p);
                    h = add2(h, s);
                }
                unpack2(h, xv[2 * z], xv[2 * z + 1]);
            }
            // guard-free scatter; silu folded into the word-0 store:
            // word0 upper half can only be v1's (wi==0) or v2's (wi==-1) high half
#pragma unroll
            for (int il = 0; il < 4; il++) {
                float x = xv[il];
                float b0, b1, b2, b3; int j;
                spline_raw(x, b0, b1, b2, b3, j);
                float base = x * sigmoidf_(x);
                uint32_t u01 = h2bits(b0, b1);
                uint32_t u23 = h2bits(b2, b3);
                int s1 = 1 + j;               // slot of first tap, in [-2, 13]
                int wi = s1 >> 1;             // word of first tap, in [-1, 6]
                bool odd = (s1 & 1) != 0;
                uint32_t v1 = odd ? (u01 << 16) : u01;
                uint32_t v2 = odd ? ((u01 >> 16) | (u23 << 16)) : u23;
                uint32_t v3 = odd ? (u23 >> 16) : 0u;
                uint32_t bb = (uint32_t)(32 * il);
                __half hs = __float2half_rn(base);
                uint32_t w0u = (wi == 0) ? (v1 & 0xFFFF0000u)
                             : ((wi == -1) ? (v2 & 0xFFFF0000u) : 0u);
                sts32(rowbase + (bb ^ swzm), (uint32_t)__half_as_ushort(hs) | w0u);
                if (wi >= 1) sts32(rowbase + ((bb + 4u * (uint32_t)wi) ^ swzm), v1);
                if (wi >= 0) sts32(rowbase + ((bb + 4u * (uint32_t)(wi + 1)) ^ swzm), v2);
                if (wi <= 5) sts32(rowbase + ((bb + 4u * (uint32_t)(wi + 2)) ^ swzm), v3);
            }
        };

        // ---- layer 1: pipelined GEMM D[32x32] = A[32x512] * B ----
        float acc[2][4][4];
#pragma unroll
        for (int mt = 0; mt < 2; mt++)
#pragma unroll
            for (int nt = 0; nt < 4; nt++)
#pragma unroll
                for (int e = 0; e < 4; e++) acc[mt][nt][e] = 0.0f;

        do_chunk(0);

#pragma unroll 1
        for (int c = 0; c < 8; c++) {
            __syncwarp();                 // scatter(c) visible to all lanes
            uint32_t afr[4][2][4];
#pragma unroll
            for (int kt = 0; kt < 4; kt++) {
                uint32_t inrow = ((uint32_t)(kt * 32 + lcolb)) ^ rmask;
                ldmatrix_x4(afr[kt][0][0], afr[kt][0][1], afr[kt][0][2], afr[kt][0][3],
                            lmA0 + inrow);
                ldmatrix_x4(afr[kt][1][0], afr[kt][1][1], afr[kt][1][2], afr[kt][1][3],
                            lmA1 + inrow);
            }
            __syncwarp();                 // all A reads done -> buffer reusable
            if (c < 7) do_chunk(c + 1);   // overlaps with mma below
#pragma unroll
            for (int kt = 0; kt < 4; kt++) {
                int ktg = c * 4 + kt;
                uint4 bv0 = __ldg(Bg + (ktg * 2 + 0) * 32);   // both np loads issued
                uint4 bv1 = __ldg(Bg + (ktg * 2 + 1) * 32);   // before dependent mmas
                mma16816(acc[0][0], afr[kt][0], bv0.x, bv0.y);
                mma16816(acc[1][0], afr[kt][1], bv0.x, bv0.y);
                mma16816(acc[0][1], afr[kt][0], bv0.z, bv0.w);
                mma16816(acc[1][1], afr[kt][1], bv0.z, bv0.w);
                mma16816(acc[0][2], afr[kt][0], bv1.x, bv1.y);
                mma16816(acc[1][2], afr[kt][1], bv1.x, bv1.y);
                mma16816(acc[0][3], afr[kt][0], bv1.z, bv1.w);
                mma16816(acc[1][3], afr[kt][1], bv1.z, bv1.w);
            }
        }

        // ---- layer 2 in fragment space (power-basis Horner) ----
        const float* S2 = smf + OFF_L2SB / 4;
        float ps[4] = {0.0f, 0.0f, 0.0f, 0.0f};
#pragma unroll
        for (int mt = 0; mt < 2; mt++)
#pragma unroll
            for (int nt = 0; nt < 4; nt++)
#pragma unroll
                for (int e = 0; e < 4; e++) {
                    float x = acc[mt][nt][e];
                    int col = nt * 8 + 2 * (lane & 3) + (e & 1);
                    float u = x * 10.0f;
                    bool inr = (u >= -3.0f) && (u < 13.0f);
                    float uc = inr ? u : 0.0f;
                    float fl = floorf(uc);
                    float t = uc - fl;
                    int r = (int)fl + 3;       // 0..15 when in range
                    float c3, c2, c1, c0;
                    lds128f(c3, c2, c1, c0,
                            sbase + OFF_L2 + (uint32_t)r * 528u + (uint32_t)col * 16u);
                    float s = fmaf(c3, t, c2);
                    s = fmaf(s, t, c1);
                    s = fmaf(s, t, c0);
                    s = inr ? s : 0.0f;
                    float base = x * sigmoidf_(x);
                    float g = fmaf(S2[col], base, s);
                    ps[mt * 2 + (e >> 1)] += g;
                }
#pragma unroll
        for (int s = 0; s < 4; s++) {
            ps[s] += __shfl_xor_sync(0xffffffffu, ps[s], 1);
            ps[s] += __shfl_xor_sync(0xffffffffu, ps[s], 2);
        }
        if ((lane & 3) == 0) {
#pragma unroll
            for (int s = 0; s < 4; s++) {
                int row = 16 * (s >> 1) + 8 * (s & 1) + (lane >> 2);
                out[pbase + row] = sigmoidf_(ps[s] + bias);
            }
        }
    }
}

extern "C" void kernel_launch(void* const* d_in, const int* in_sizes, int n_in,
                              void* d_out, int out_size)
{
    // order: coords, grid0, coef0, sb0, sp0, grid1, coef1, sb1, sp1, grid2, coef2, sb2, sp2, density_bias
    const float* coords = (const float*)d_in[0];
    const float* coef0  = (const float*)d_in[2];
    const float* sb0    = (const float*)d_in[3];
    const float* sp0    = (const float*)d_in[4];
    const float* coef1  = (const float*)d_in[6];
    const float* sb1    = (const float*)d_in[7];
    const float* sp1    = (const float*)d_in[8];
    const float* coef2  = (const float*)d_in[10];
    const float* sb2    = (const float*)d_in[11];
    const float* sp2    = (const float*)d_in[12];
    const float* dbias  = (const float*)d_in[13];
    float* out = (float*)d_out;

    bfrag_init<<<64, 128>>>(sb1, sp1, coef1);
    cudaFuncSetAttribute(kan_forward, cudaFuncAttributeMaxDynamicSharedMemorySize, SMEM_BYTES);
    kan_forward<<<BLOCKS, THREADS, SMEM_BYTES>>>(coords,
                                                 coef0, sb0, sp0,
                                                 coef2, sb2, sp2,
                                                 dbias, out);
}

// round 16
// speedup vs baseline: 1.1298x; 1.1005x over previous
#include <cuda_runtime.h>
#include <cuda_fp16.h>
#include <cstdint>

#define THREADS 128
#define BLOCKS  740               // 148 SMs * 5 CTAs, single wave
#define NPTS    (512 * 512)
#define NTILES  2048              // 128 points per block-tile

// ---- smem byte layout ----
#define OFF_ABUF  0               // 4 warps x 32 rows x 128B = 16384
#define OFF_L0    16384           // power-basis L0: 2 i x 10 j x 528B = 10560
#define OFF_L0SB  26944           // sb0 pairs: 2 i x 16 q x 8B = 256
#define OFF_L2    27200           // power-basis L2: 16 rows x 528B = 8448
#define OFF_L2SB  35648           // 32 f32 = 128
#define SMEM_BYTES 35776          // x5 CTAs = 178880

// B fragments live in global, cached in L1 (shared by all CTAs on an SM)
__device__ uint32_t g_bfrag[8192];

// ---------------- helpers ----------------
typedef unsigned long long u64;
__device__ __forceinline__ uint32_t smem_u32(const void* p) {
    uint32_t a;
    asm("{ .reg .u64 t; cvta.to.shared.u64 t, %1; cvt.u32.u64 %0, t; }" : "=r"(a) : "l"(p));
    return a;
}
__device__ __forceinline__ void sts32(uint32_t a, uint32_t v) {
    asm volatile("st.shared.b32 [%0], %1;" :: "r"(a), "r"(v) : "memory");
}
__device__ __forceinline__ void sts16(uint32_t a, uint16_t v) {
    asm volatile("st.shared.b16 [%0], %1;" :: "r"(a), "h"(v) : "memory");
}
__device__ __forceinline__ void sts128z(uint32_t a) {
    asm volatile("st.shared.v4.b32 [%0], {%1,%1,%1,%1};" :: "r"(a), "r"(0u) : "memory");
}
__device__ __forceinline__ void lds128f(float& a, float& b, float& c, float& d, uint32_t addr) {
    asm volatile("ld.shared.v4.f32 {%0,%1,%2,%3}, [%4];"
                 : "=f"(a), "=f"(b), "=f"(c), "=f"(d) : "r"(addr));
}
__device__ __forceinline__ void lds128u64(u64& a, u64& b, uint32_t addr) {
    asm volatile("ld.shared.v2.b64 {%0,%1}, [%2];" : "=l"(a), "=l"(b) : "r"(addr));
}
__device__ __forceinline__ u64 lds_b64(uint32_t a) {
    u64 v;
    asm volatile("ld.shared.b64 %0, [%1];" : "=l"(v) : "r"(a));
    return v;
}
__device__ __forceinline__ void ldmatrix_x4(uint32_t& r0, uint32_t& r1, uint32_t& r2, uint32_t& r3,
                                            uint32_t addr) {
    asm volatile("ldmatrix.sync.aligned.m8n8.x4.shared.b16 {%0,%1,%2,%3}, [%4];"
                 : "=r"(r0), "=r"(r1), "=r"(r2), "=r"(r3) : "r"(addr));
}
__device__ __forceinline__ void mma16816(float* d, const uint32_t* a, uint32_t b0, uint32_t b1) {
    asm volatile("mma.sync.aligned.m16n8k16.row.col.f32.f16.f16.f32 "
                 "{%0,%1,%2,%3}, {%4,%5,%6,%7}, {%8,%9}, {%0,%1,%2,%3};"
                 : "+f"(d[0]), "+f"(d[1]), "+f"(d[2]), "+f"(d[3])
                 : "r"(a[0]), "r"(a[1]), "r"(a[2]), "r"(a[3]), "r"(b0), "r"(b1));
}
__device__ __forceinline__ u64 pack2(float lo, float hi) {
    u64 r;
    asm("mov.b64 %0, {%1,%2};" : "=l"(r) : "f"(lo), "f"(hi));
    return r;
}
__device__ __forceinline__ void fma2(u64& acc, u64 a, u64 b) {
    asm("fma.rn.f32x2 %0, %1, %2, %0;" : "+l"(acc) : "l"(a), "l"(b));
}
__device__ __forceinline__ u64 fma2g(u64 a, u64 b, u64 c) {
    u64 d;
    asm("fma.rn.f32x2 %0, %1, %2, %3;" : "=l"(d) : "l"(a), "l"(b), "l"(c));
    return d;
}
__device__ __forceinline__ u64 add2(u64 a, u64 b) {
    u64 d;
    asm("add.rn.f32x2 %0, %1, %2;" : "=l"(d) : "l"(a), "l"(b));
    return d;
}
__device__ __forceinline__ void unpack2(u64 v, float& lo, float& hi) {
    asm("mov.b64 {%0,%1}, %2;" : "=f"(lo), "=f"(hi) : "l"(v));
}
__device__ __forceinline__ float sigmoidf_(float x) { return 1.0f / (1.0f + __expf(-x)); }
__device__ __forceinline__ uint32_t h2bits(float lo, float hi) {
    __half2 h = __floats2half2_rn(lo, hi);
    return *reinterpret_cast<uint32_t*>(&h);
}

// raw uniform cubic B-spline polys (no tap zeroing); oor -> j=-3, t=0
__device__ __forceinline__ void spline_raw(float x, float& b0, float& b1, float& b2, float& b3,
                                           int& j)
{
    float u = x * 10.0f;
    bool inr = (u >= -3.0f) && (u < 13.0f);
    float uc = inr ? u : 0.0f;
    float f = floorf(uc);
    float t = uc - f;
    j = inr ? (int)f : -3;
    if (!inr) t = 0.0f;
    const float C6 = 0.16666667f;
    float t2 = t * t, t3 = t2 * t;
    float omt = 1.0f - t;
    b0 = omt * omt * omt * C6;
    b1 = (3.0f * t3 - 6.0f * t2 + 4.0f) * C6;
    b2 = ((3.0f - 3.0f * t) * t2 + 3.0f * t + 1.0f) * C6;
    b3 = t3 * C6;
}

// power-basis coefficients from 4 taps C0..C3 (spline = c0 + c1 t + c2 t^2 + c3 t^3)
__device__ __forceinline__ void pb_coeffs(const float* C, float& c0, float& c1, float& c2, float& c3)
{
    const float C6 = 0.16666667f;
    c0 = (C[0] + 4.0f * C[1] + C[2]) * C6;
    c1 = (C[2] - C[0]) * 0.5f;
    c2 = (C[0] - 2.0f * C[1] + C[2]) * 0.5f;
    c3 = (-C[0] + 3.0f * C[1] - 3.0f * C[2] + C[3]) * C6;
}

// ---------------- init kernel: stage B fragments to global ----------------
__global__ void bfrag_init(const float* __restrict__ sb1, const float* __restrict__ sp1,
                           const float* __restrict__ coef1)
{
    int e = blockIdx.x * blockDim.x + threadIdx.x;
    if (e >= 8192) return;
    int L = e & 31, reg = (e >> 5) & 1, nt = (e >> 6) & 3, kt = e >> 8;
    int k = kt * 16 + 2 * (L & 3) + 8 * reg;
    int n = nt * 8 + (L >> 2);
    float w[2];
#pragma unroll
    for (int z = 0; z < 2; z++) {
        int f = k + z;
        int i = f >> 4, r = f & 15;
        float v = 0.0f;
        if (r == 0)       v = sb1[i * 32 + n];
        else if (r <= 13) v = sp1[i * 32 + n] * coef1[(i * 32 + n) * 13 + (r - 1)];
        w[z] = v;
    }
    g_bfrag[(kt * 2 + (nt >> 1)) * 128 + L * 4 + (nt & 1) * 2 + reg] = h2bits(w[0], w[1]);
}

// ---------------- main kernel ----------------
__global__ void __launch_bounds__(THREADS, 5)
kan_forward(const float* __restrict__ coords,
            const float* __restrict__ coef0, const float* __restrict__ sb0, const float* __restrict__ sp0,
            const float* __restrict__ coef2, const float* __restrict__ sb2, const float* __restrict__ sp2,
            const float* __restrict__ dbias,
            float* __restrict__ out)
{
    extern __shared__ char smem[];
    float* smf = reinterpret_cast<float*>(smem);
    const uint32_t sbase = smem_u32(smem);
    const int tid  = threadIdx.x;
    const int wid  = tid >> 5;
    const int lane = tid & 31;

    // ======== one-time staging ========
    // L0 power-basis: [i][j][q]{c3,c3',c2,c2',c1,c1',c0,c0'}; j stride 528B
    for (int idx = tid; idx < 320; idx += THREADS) {
        int i = idx / 160, r = idx % 160, j = r / 16, q = r % 16;
        int fo = (OFF_L0 + i * 5280 + j * 528 + q * 32) / 4;
#pragma unroll
        for (int z = 0; z < 2; z++) {
            int o = 2 * q + z;
            float C[4];
#pragma unroll
            for (int d = 0; d < 4; d++)
                C[d] = sp0[i * 32 + o] * coef0[(i * 32 + o) * 13 + j + d];
            float c0, c1, c2, c3;
            pb_coeffs(C, c0, c1, c2, c3);
            smf[fo + 0 + z] = c3;
            smf[fo + 2 + z] = c2;
            smf[fo + 4 + z] = c1;
            smf[fo + 6 + z] = c0;
        }
    }
    // L0 sb pairs
    for (int idx = tid; idx < 32; idx += THREADS) {
        int i = idx / 16, q = idx % 16;
        smf[(OFF_L0SB + i * 128 + q * 8) / 4 + 0] = sb0[i * 32 + 2 * q];
        smf[(OFF_L0SB + i * 128 + q * 8) / 4 + 1] = sb0[i * 32 + 2 * q + 1];
    }
    // L2 power-basis: [row 0..15][col]{c3,c2,c1,c0}; row stride 528B; C zero-extended
    for (int idx = tid; idx < 512; idx += THREADS) {
        int r = idx >> 5, col = idx & 31, j = r - 3;
        float C[4];
#pragma unroll
        for (int d = 0; d < 4; d++) {
            int k = j + d;
            C[d] = (k >= 0 && k <= 12) ? sp2[col] * coef2[col * 13 + k] : 0.0f;
        }
        float c0, c1, c2, c3;
        pb_coeffs(C, c0, c1, c2, c3);
        int fo = (OFF_L2 + r * 528 + col * 16) / 4;
        smf[fo + 0] = c3;
        smf[fo + 1] = c2;
        smf[fo + 2] = c1;
        smf[fo + 3] = c0;
    }
    for (int idx = tid; idx < 32; idx += THREADS)
        smf[OFF_L2SB / 4 + idx] = sb2[idx];
    __syncthreads();

    const float bias = dbias[0];
    const uint32_t ABw     = sbase + OFF_ABUF + (uint32_t)wid * 4096u;
    const uint32_t rowbase = ABw + (uint32_t)lane * 128u;
    const uint32_t swzm    = (uint32_t)(lane & 7) << 4;
    const int lrow  = lane & 15;
    const int lcolb = (lane >> 4) * 16;
    const uint32_t rmask = (uint32_t)(lrow & 7) << 4;
    const uint32_t lmA0 = ABw + (uint32_t)lrow * 128u;
    const uint32_t lmA1 = ABw + (uint32_t)(16 + lrow) * 128u;
    const uint4* Bg = reinterpret_cast<const uint4*>(g_bfrag) + lane;
    const float2* coords2 = reinterpret_cast<const float2*>(coords);

    // rolling coords prefetch: load for first tile now
    float2 cc = coords2[blockIdx.x * 128 + wid * 32 + lane];

    for (int tile = blockIdx.x; tile < NTILES; tile += BLOCKS) {
        const int pbase = tile * 128 + wid * 32;

        // ---- layer-0 prep (coords in [0,1) -> j in 0..9) ----
        u64 tp[2], bp[2];
        uint32_t Tr[2];
#pragma unroll
        for (int i = 0; i < 2; i++) {
            float x = (i == 0) ? cc.x : cc.y;
            float u = x * 10.0f;
            float fl = floorf(u);
            float t = u - fl;
            int j = (int)fl;
            tp[i] = pack2(t, t);
            float base = x * sigmoidf_(x);
            bp[i] = pack2(base, base);
            Tr[i] = sbase + OFF_L0 + (uint32_t)i * 5280u + (uint32_t)j * 528u;
        }

        // prefetch next tile's coords (latency hides under the GEMM below)
        if (tile + BLOCKS < NTILES)
            cc = coords2[(tile + BLOCKS) * 128 + wid * 32 + lane];

        // zero + compute h1 (4 outputs, Horner power basis) + scatter, for chunk cidx
        auto do_chunk = [&](int cidx) {
#pragma unroll
            for (int q = 0; q < 8; q++)
                sts128z(rowbase + (((uint32_t)q * 16u) ^ swzm));
            float xv[4];
#pragma unroll
            for (int z = 0; z < 2; z++) {
                uint32_t qi = (uint32_t)(2 * cidx + z);
                uint32_t off = qi * 32u;
                u64 h = 0ull;
#pragma unroll
                for (int i = 0; i < 2; i++) {
                    u64 sbp = lds_b64(sbase + OFF_L0SB + (uint32_t)i * 128u + qi * 8u);
                    fma2(h, bp[i], sbp);
                    u64 c3p, c2p, c1p, c0p;
                    lds128u64(c3p, c2p, Tr[i] + off);
                    lds128u64(c1p, c0p, Tr[i] + off + 16u);
                    u64 s = fma2g(c3p, tp[i], c2p);
                    s = fma2g(s, tp[i], c1p);
                    s = fma2g(s, tp[i], c0p);
                    h = add2(h, s);
                }
                unpack2(h, xv[2 * z], xv[2 * z + 1]);
            }
            // guard-free scatter (invalid taps absorbed by wi store-guards, dummy slots,
            // or slot 0 which the silu store overwrites last)
#pragma unroll
            for (int il = 0; il < 4; il++) {
                float x = xv[il];
                float b0, b1, b2, b3; int j;
                spline_raw(x, b0, b1, b2, b3, j);
                float base = x * sigmoidf_(x);
                uint32_t u01 = h2bits(b0, b1);
                uint32_t u23 = h2bits(b2, b3);
                int s1 = 1 + j;               // slot of first tap, in [-2, 13]
                int wi = s1 >> 1;             // word of first tap, in [-1, 6]
                bool odd = (s1 & 1) != 0;
                uint32_t v1 = odd ? (u01 << 16) : u01;
                uint32_t v2 = odd ? ((u01 >> 16) | (u23 << 16)) : u23;
                uint32_t v3 = odd ? (u23 >> 16) : 0u;
                uint32_t bb = (uint32_t)(32 * il);
                if (wi >= 0) sts32(rowbase + ((bb + 4u * (uint32_t)wi) ^ swzm), v1);
                sts32(rowbase + ((bb + 4u * (uint32_t)(wi + 1)) ^ swzm), v2);
                if (wi <= 5) sts32(rowbase + ((bb + 4u * (uint32_t)(wi + 2)) ^ swzm), v3);
                __half hs = __float2half_rn(base);
                sts16(rowbase + (bb ^ swzm), __half_as_ushort(hs));
            }
        };

        // ---- layer 1: pipelined GEMM D[32x32] = A[32x512] * B ----
        float acc[2][4][4];
#pragma unroll
        for (int mt = 0; mt < 2; mt++)
#pragma unroll
            for (int nt = 0; nt < 4; nt++)
#pragma unroll
                for (int e = 0; e < 4; e++) acc[mt][nt][e] = 0.0f;

        do_chunk(0);

#pragma unroll 1
        for (int c = 0; c < 8; c++) {
            __syncwarp();                 // scatter(c) visible to all lanes
            uint32_t afr[4][2][4];
#pragma unroll
            for (int kt = 0; kt < 4; kt++) {
                uint32_t inrow = ((uint32_t)(kt * 32 + lcolb)) ^ rmask;
                ldmatrix_x4(afr[kt][0][0], afr[kt][0][1], afr[kt][0][2], afr[kt][0][3],
                            lmA0 + inrow);
                ldmatrix_x4(afr[kt][1][0], afr[kt][1][1], afr[kt][1][2], afr[kt][1][3],
                            lmA1 + inrow);
            }
            __syncwarp();                 // all A reads done -> buffer reusable
            if (c < 7) do_chunk(c + 1);   // overlaps with mma below
#pragma unroll
            for (int kt = 0; kt < 4; kt++) {
                int ktg = c * 4 + kt;
#pragma unroll
                for (int np = 0; np < 2; np++) {
                    uint4 bv = __ldg(Bg + (ktg * 2 + np) * 32);
                    mma16816(acc[0][2 * np],     afr[kt][0], bv.x, bv.y);
                    mma16816(acc[1][2 * np],     afr[kt][1], bv.x, bv.y);
                    mma16816(acc[0][2 * np + 1], afr[kt][0], bv.z, bv.w);
                    mma16816(acc[1][2 * np + 1], afr[kt][1], bv.z, bv.w);
                }
            }
        }

        // ---- layer 2 in fragment space (power-basis Horner) ----
        const float* S2 = smf + OFF_L2SB / 4;
        float ps[4] = {0.0f, 0.0f, 0.0f, 0.0f};
#pragma unroll
        for (int mt = 0; mt < 2; mt++)
#pragma unroll
            for (int nt = 0; nt < 4; nt++)
#pragma unroll
                for (int e = 0; e < 4; e++) {
                    float x = acc[mt][nt][e];
                    int col = nt * 8 + 2 * (lane & 3) + (e & 1);
                    float u = x * 10.0f;
                    bool inr = (u >= -3.0f) && (u < 13.0f);
                    float uc = inr ? u : 0.0f;
                    float fl = floorf(uc);
                    float t = uc - fl;
                    int r = (int)fl + 3;       // 0..15 when in range
                    float c3, c2, c1, c0;
                    lds128f(c3, c2, c1, c0,
                            sbase + OFF_L2 + (uint32_t)r * 528u + (uint32_t)col * 16u);
                    float s = fmaf(c3, t, c2);
                    s = fmaf(s, t, c1);
                    s = fmaf(s, t, c0);
                    s = inr ? s : 0.0f;
                    float base = x * sigmoidf_(x);
                    float g = fmaf(S2[col], base, s);
                    ps[mt * 2 + (e >> 1)] += g;
                }
#pragma unroll
        for (int s = 0; s < 4; s++) {
            ps[s] += __shfl_xor_sync(0xffffffffu, ps[s], 1);
            ps[s] += __shfl_xor_sync(0xffffffffu, ps[s], 2);
        }
        if ((lane & 3) == 0) {
#pragma unroll
            for (int s = 0; s < 4; s++) {
                int row = 16 * (s >> 1) + 8 * (s & 1) + (lane >> 2);
                out[pbase + row] = sigmoidf_(ps[s] + bias);
            }
        }
    }
}

extern "C" void kernel_launch(void* const* d_in, const int* in_sizes, int n_in,
                              void* d_out, int out_size)
{
    // order: coords, grid0, coef0, sb0, sp0, grid1, coef1, sb1, sp1, grid2, coef2, sb2, sp2, density_bias
    const float* coords = (const float*)d_in[0];
    const float* coef0  = (const float*)d_in[2];
    const float* sb0    = (const float*)d_in[3];
    const float* sp0    = (const float*)d_in[4];
    const float* coef1  = (const float*)d_in[6];
    const float* sb1    = (const float*)d_in[7];
    const float* sp1    = (const float*)d_in[8];
    const float* coef2  = (const float*)d_in[10];
    const float* sb2    = (const float*)d_in[11];
    const float* sp2    = (const float*)d_in[12];
    const float* dbias  = (const float*)d_in[13];
    float* out = (float*)d_out;

    bfrag_init<<<64, 128>>>(sb1, sp1, coef1);
    cudaFuncSetAttribute(kan_forward, cudaFuncAttributeMaxDynamicSharedMemorySize, SMEM_BYTES);
    kan_forward<<<BLOCKS, THREADS, SMEM_BYTES>>>(coords,
                                                 coef0, sb0, sp0,
                                                 coef2, sb2, sp2,
                                                 dbias, out);
}